// round 7
// baseline (speedup 1.0000x reference)
#include <cuda_runtime.h>

#define BB 32
#define SS 2048
#define VV 256
#define EE 512
#define HH 1024
#define KK 16

typedef unsigned long long u64;

__device__ __align__(256) float g_G[(VV + 1) * KK * HH];
__device__ __align__(256) float g_L1[VV * VV];
__device__ __align__(256) float g_act[(size_t)BB * SS * HH];

__device__ __forceinline__ u64 pack2(float lo, float hi) {
    u64 r; asm("mov.b64 %0,{%1,%2};" : "=l"(r) : "f"(lo), "f"(hi)); return r;
}
__device__ __forceinline__ void unpack2(u64 p, float& lo, float& hi) {
    asm("mov.b64 {%0,%1},%2;" : "=f"(lo), "=f"(hi) : "l"(p));
}
__device__ __forceinline__ u64 ffma2(u64 a, u64 b, u64 c) {
    u64 d; asm("fma.rn.f32x2 %0,%1,%2,%3;" : "=l"(d) : "l"(a), "l"(b), "l"(c)); return d;
}

// L1[vt][v] = emb[vt,:] . lin_w[v,0:512]
__global__ __launch_bounds__(256) void k_L1(const float* __restrict__ emb,
                                            const float* __restrict__ lin_w) {
    __shared__ __align__(16) float4 s_emb[EE / 4];
    const int vt = blockIdx.x, tid = threadIdx.x;
    if (tid < EE / 4) s_emb[tid] = ((const float4*)(emb + (size_t)vt * EE))[tid];
    __syncthreads();
    const int lane = tid & 31, warp = tid >> 5;
    for (int v = warp; v < VV; v += 8) {
        const float4* w4 = (const float4*)(lin_w + (size_t)v * (EE + HH));
        float s = 0.f;
#pragma unroll
        for (int i = 0; i < 4; ++i) {
            float4 a = s_emb[lane + 32 * i];
            float4 b = w4[lane + 32 * i];
            s += a.x * b.x + a.y * b.y + a.z * b.z + a.w * b.w;
        }
#pragma unroll
        for (int off = 16; off; off >>= 1) s += __shfl_xor_sync(0xffffffffu, s, off);
        if (lane == 0) g_L1[vt * VV + v] = s;
    }
}

// zero pad row G[VV][*][*]
__global__ __launch_bounds__(256) void k_zero() {
    ((float4*)(g_G + (size_t)VV * KK * HH))[blockIdx.x * 256 + threadIdx.x] =
        make_float4(0.f, 0.f, 0.f, 0.f);
}

// G[v][k][h] = sum_e emb[v,e] * conv_w[h,e,k]
__global__ __launch_bounds__(256) void k_G(const float* __restrict__ emb,
                                           const float* __restrict__ conv_w) {
    __shared__ __align__(16) float s_a[8 * 8];
    __shared__ __align__(16) float s_b[8 * KK * 64];
    const int h0 = blockIdx.x * 64, v0 = blockIdx.y * 8, tid = threadIdx.x;
    const int k = tid >> 4, hq = tid & 15;
    const int hl = tid >> 2, q = tid & 3;
    float acc[8][4];
#pragma unroll
    for (int v = 0; v < 8; ++v)
#pragma unroll
        for (int j = 0; j < 4; ++j) acc[v][j] = 0.f;

    for (int e0 = 0; e0 < EE; e0 += 8) {
        if (tid < 64) {
            int e = tid >> 3, v = tid & 7;
            s_a[e * 8 + v] = emb[(size_t)(v0 + v) * EE + e0 + e];
        }
#pragma unroll
        for (int e = 0; e < 8; ++e) {
            float4 w4 = *(const float4*)(conv_w + (size_t)(h0 + hl) * (EE * KK) +
                                         (e0 + e) * KK + q * 4);
            s_b[(e * KK + q * 4 + 0) * 64 + hl] = w4.x;
            s_b[(e * KK + q * 4 + 1) * 64 + hl] = w4.y;
            s_b[(e * KK + q * 4 + 2) * 64 + hl] = w4.z;
            s_b[(e * KK + q * 4 + 3) * 64 + hl] = w4.w;
        }
        __syncthreads();
#pragma unroll
        for (int e = 0; e < 8; ++e) {
            float4 a0 = *(const float4*)(s_a + e * 8);
            float4 a1 = *(const float4*)(s_a + e * 8 + 4);
            float a_[8] = {a0.x, a0.y, a0.z, a0.w, a1.x, a1.y, a1.z, a1.w};
            float4 bb = *(const float4*)(s_b + (e * KK + k) * 64 + hq * 4);
#pragma unroll
            for (int v = 0; v < 8; ++v) {
                acc[v][0] += a_[v] * bb.x;
                acc[v][1] += a_[v] * bb.y;
                acc[v][2] += a_[v] * bb.z;
                acc[v][3] += a_[v] * bb.w;
            }
        }
        __syncthreads();
    }
#pragma unroll
    for (int v = 0; v < 8; ++v)
        *(float4*)(g_G + (size_t)((v0 + v) * KK + k) * HH + h0 + hq * 4) =
            make_float4(acc[v][0], acc[v][1], acc[v][2], acc[v][3]);
}

// act[b,t,h] = relu(conv_b[h] + sum_k G[tok[t-15+k]][k][h]); one warp per timestep
__global__ __launch_bounds__(256) void k_conv(const int* __restrict__ tok,
                                              const float* __restrict__ conv_b) {
    __shared__ int s_tok[24];
    __shared__ __align__(16) float s_cb[HH];
    const int tile = blockIdx.x;
    const int b = tile >> 8;           // S/8 = 256 tiles per batch
    const int t0 = (tile & 255) << 3;
    const int tid = threadIdx.x, lane = tid & 31, warp = tid >> 5;

    if (tid < 23) {
        int p = t0 - 15 + tid;
        s_tok[tid] = (p < 0) ? VV : tok[b * SS + p];
    }
    ((float4*)s_cb)[tid] = ((const float4*)conv_b)[tid]; // 256 * 4 = 1024
    __syncthreads();

    float4 acc[8];
#pragma unroll
    for (int i = 0; i < 8; ++i) acc[i] = ((const float4*)s_cb)[lane + 32 * i];

#pragma unroll 2
    for (int k = 0; k < KK; ++k) {
        const int v = s_tok[warp + k];
        const float4* row = (const float4*)(g_G + (size_t)(v * KK + k) * HH);
#pragma unroll
        for (int i = 0; i < 8; ++i) {
            float4 r = row[lane + 32 * i];
            acc[i].x += r.x; acc[i].y += r.y; acc[i].z += r.z; acc[i].w += r.w;
        }
    }
    float4* orow = (float4*)(g_act + (size_t)(b * SS + t0 + warp) * HH);
#pragma unroll
    for (int i = 0; i < 8; ++i)
        orow[lane + 32 * i] = make_float4(fmaxf(acc[i].x, 0.f), fmaxf(acc[i].y, 0.f),
                                          fmaxf(acc[i].z, 0.f), fmaxf(acc[i].w, 0.f));
}

// logits = L1[tok[row]] + lin_b + act[row]·lin_w[:,512:], then softmax.
// CTA tile: 32 rows x 256 v. warp owns 4 rows; lane owns v0=lane*8.
__global__ __launch_bounds__(256) void k_lin(const int* __restrict__ tok,
                                             const float* __restrict__ lin_w,
                                             const float* __restrict__ lin_b,
                                             float* __restrict__ out) {
    __shared__ __align__(16) float s_a[32 * 32];
    __shared__ __align__(16) float s_w[32 * 256];
    const int row0 = blockIdx.x * 32, tid = threadIdx.x;
    const int lane = tid & 31, warp = tid >> 5, v0 = lane * 8;

    u64 acc[4][4];
    const float4 lb0 = *(const float4*)(lin_b + v0);
    const float4 lb1 = *(const float4*)(lin_b + v0 + 4);
#pragma unroll
    for (int j = 0; j < 4; ++j) {
        const int vt = tok[row0 + warp * 4 + j];
        float4 p0 = *(const float4*)(g_L1 + vt * VV + v0);
        float4 p1 = *(const float4*)(g_L1 + vt * VV + v0 + 4);
        acc[j][0] = pack2(p0.x + lb0.x, p0.y + lb0.y);
        acc[j][1] = pack2(p0.z + lb0.z, p0.w + lb0.w);
        acc[j][2] = pack2(p1.x + lb1.x, p1.y + lb1.y);
        acc[j][3] = pack2(p1.z + lb1.z, p1.w + lb1.w);
    }

    const int ra = tid >> 3, pa = tid & 7;
    for (int h0 = 0; h0 < HH; h0 += 32) {
        *(float4*)(s_a + ra * 32 + pa * 4) =
            *(const float4*)(g_act + (size_t)(row0 + ra) * HH + h0 + pa * 4);
        const float* wr = lin_w + (size_t)tid * (EE + HH) + EE + h0;
#pragma unroll
        for (int j2 = 0; j2 < 8; ++j2) {
            float4 c = *(const float4*)(wr + j2 * 4);
            s_w[(j2 * 4 + 0) * 256 + tid] = c.x;
            s_w[(j2 * 4 + 1) * 256 + tid] = c.y;
            s_w[(j2 * 4 + 2) * 256 + tid] = c.z;
            s_w[(j2 * 4 + 3) * 256 + tid] = c.w;
        }
        __syncthreads();
#pragma unroll
        for (int kk = 0; kk < 32; ++kk) {
            ulonglong2 wa = *(const ulonglong2*)(s_w + kk * 256 + v0);
            ulonglong2 wb = *(const ulonglong2*)(s_w + kk * 256 + v0 + 4);
#pragma unroll
            for (int j = 0; j < 4; ++j) {
                float a = s_a[(warp * 4 + j) * 32 + kk];
                u64 ap = pack2(a, a);
                acc[j][0] = ffma2(ap, wa.x, acc[j][0]);
                acc[j][1] = ffma2(ap, wa.y, acc[j][1]);
                acc[j][2] = ffma2(ap, wb.x, acc[j][2]);
                acc[j][3] = ffma2(ap, wb.y, acc[j][3]);
            }
        }
        __syncthreads();
    }

#pragma unroll
    for (int j = 0; j < 4; ++j) {
        float v[8];
        unpack2(acc[j][0], v[0], v[1]); unpack2(acc[j][1], v[2], v[3]);
        unpack2(acc[j][2], v[4], v[5]); unpack2(acc[j][3], v[6], v[7]);
        float m = v[0];
#pragma unroll
        for (int i = 1; i < 8; ++i) m = fmaxf(m, v[i]);
#pragma unroll
        for (int off = 16; off; off >>= 1) m = fmaxf(m, __shfl_xor_sync(0xffffffffu, m, off));
        float s = 0.f;
#pragma unroll
        for (int i = 0; i < 8; ++i) { v[i] = __expf(v[i] - m); s += v[i]; }
#pragma unroll
        for (int off = 16; off; off >>= 1) s += __shfl_xor_sync(0xffffffffu, s, off);
        const float inv = __frcp_rn(s);
        float* op = out + (size_t)(row0 + warp * 4 + j) * VV + v0;
        *(float4*)op = make_float4(v[0] * inv, v[1] * inv, v[2] * inv, v[3] * inv);
        *(float4*)(op + 4) = make_float4(v[4] * inv, v[5] * inv, v[6] * inv, v[7] * inv);
    }
}

extern "C" void kernel_launch(void* const* d_in, const int* in_sizes, int n_in,
                              void* d_out, int out_size) {
    const int*   tok    = (const int*)d_in[0];
    const float* emb    = (const float*)d_in[1];
    const float* conv_w = (const float*)d_in[2];
    const float* conv_b = (const float*)d_in[3];
    const float* lin_w  = (const float*)d_in[4];
    const float* lin_b  = (const float*)d_in[5];
    float* out = (float*)d_out;

    k_L1<<<VV, 256>>>(emb, lin_w);
    k_zero<<<16, 256>>>();
    k_G<<<dim3(HH / 64, VV / 8), 256>>>(emb, conv_w);
    k_conv<<<(BB * SS) / 8, 256>>>(tok, conv_b);
    k_lin<<<(BB * SS) / 32, 256>>>(tok, lin_w, lin_b, out);
}

// round 8
// speedup vs baseline: 1.0025x; 1.0025x over previous
#include <cuda_runtime.h>

#define BB 32
#define SS 2048
#define VV 256
#define EE 512
#define HH 1024
#define KK 16

typedef unsigned long long u64;

__device__ __align__(256) float g_G[(VV + 1) * KK * HH];
__device__ __align__(256) float g_L1[VV * VV];
__device__ __align__(256) float g_act[(size_t)BB * SS * HH];

__device__ __forceinline__ u64 pack2(float lo, float hi) {
    u64 r; asm("mov.b64 %0,{%1,%2};" : "=l"(r) : "f"(lo), "f"(hi)); return r;
}
__device__ __forceinline__ void unpack2(u64 p, float& lo, float& hi) {
    asm("mov.b64 {%0,%1},%2;" : "=f"(lo), "=f"(hi) : "l"(p));
}
__device__ __forceinline__ u64 ffma2(u64 a, u64 b, u64 c) {
    u64 d; asm("fma.rn.f32x2 %0,%1,%2,%3;" : "=l"(d) : "l"(a), "l"(b), "l"(c)); return d;
}

// L1[vt][v] = emb[vt,:] . lin_w[v,0:512]
__global__ __launch_bounds__(256) void k_L1(const float* __restrict__ emb,
                                            const float* __restrict__ lin_w) {
    __shared__ __align__(16) float4 s_emb[EE / 4];
    const int vt = blockIdx.x, tid = threadIdx.x;
    if (tid < EE / 4) s_emb[tid] = ((const float4*)(emb + (size_t)vt * EE))[tid];
    __syncthreads();
    const int lane = tid & 31, warp = tid >> 5;
    for (int v = warp; v < VV; v += 8) {
        const float4* w4 = (const float4*)(lin_w + (size_t)v * (EE + HH));
        float s = 0.f;
#pragma unroll
        for (int i = 0; i < 4; ++i) {
            float4 a = s_emb[lane + 32 * i];
            float4 b = w4[lane + 32 * i];
            s += a.x * b.x + a.y * b.y + a.z * b.z + a.w * b.w;
        }
#pragma unroll
        for (int off = 16; off; off >>= 1) s += __shfl_xor_sync(0xffffffffu, s, off);
        if (lane == 0) g_L1[vt * VV + v] = s;
    }
}

// zero pad row G[VV][*][*]
__global__ __launch_bounds__(256) void k_zero() {
    ((float4*)(g_G + (size_t)VV * KK * HH))[blockIdx.x * 256 + threadIdx.x] =
        make_float4(0.f, 0.f, 0.f, 0.f);
}

// G[v][k][h] = sum_e emb[v,e] * conv_w[h,e,k]
__global__ __launch_bounds__(256) void k_G(const float* __restrict__ emb,
                                           const float* __restrict__ conv_w) {
    __shared__ __align__(16) float s_a[8 * 8];
    __shared__ __align__(16) float s_b[8 * KK * 64];
    const int h0 = blockIdx.x * 64, v0 = blockIdx.y * 8, tid = threadIdx.x;
    const int k = tid >> 4, hq = tid & 15;
    const int hl = tid >> 2, q = tid & 3;
    float acc[8][4];
#pragma unroll
    for (int v = 0; v < 8; ++v)
#pragma unroll
        for (int j = 0; j < 4; ++j) acc[v][j] = 0.f;

    for (int e0 = 0; e0 < EE; e0 += 8) {
        if (tid < 64) {
            int e = tid >> 3, v = tid & 7;
            s_a[e * 8 + v] = emb[(size_t)(v0 + v) * EE + e0 + e];
        }
#pragma unroll
        for (int e = 0; e < 8; ++e) {
            float4 w4 = *(const float4*)(conv_w + (size_t)(h0 + hl) * (EE * KK) +
                                         (e0 + e) * KK + q * 4);
            s_b[(e * KK + q * 4 + 0) * 64 + hl] = w4.x;
            s_b[(e * KK + q * 4 + 1) * 64 + hl] = w4.y;
            s_b[(e * KK + q * 4 + 2) * 64 + hl] = w4.z;
            s_b[(e * KK + q * 4 + 3) * 64 + hl] = w4.w;
        }
        __syncthreads();
#pragma unroll
        for (int e = 0; e < 8; ++e) {
            float4 a0 = *(const float4*)(s_a + e * 8);
            float4 a1 = *(const float4*)(s_a + e * 8 + 4);
            float a_[8] = {a0.x, a0.y, a0.z, a0.w, a1.x, a1.y, a1.z, a1.w};
            float4 bb = *(const float4*)(s_b + (e * KK + k) * 64 + hq * 4);
#pragma unroll
            for (int v = 0; v < 8; ++v) {
                acc[v][0] += a_[v] * bb.x;
                acc[v][1] += a_[v] * bb.y;
                acc[v][2] += a_[v] * bb.z;
                acc[v][3] += a_[v] * bb.w;
            }
        }
        __syncthreads();
    }
#pragma unroll
    for (int v = 0; v < 8; ++v)
        *(float4*)(g_G + (size_t)((v0 + v) * KK + k) * HH + h0 + hq * 4) =
            make_float4(acc[v][0], acc[v][1], acc[v][2], acc[v][3]);
}

// act[b,t,h] = relu(conv_b[h] + sum_k G[tok[t-15+k]][k][h]); one warp per timestep
__global__ __launch_bounds__(256) void k_conv(const int* __restrict__ tok,
                                              const float* __restrict__ conv_b) {
    __shared__ int s_tok[24];
    __shared__ __align__(16) float s_cb[HH];
    const int tile = blockIdx.x;
    const int b = tile >> 8;           // S/8 = 256 tiles per batch
    const int t0 = (tile & 255) << 3;
    const int tid = threadIdx.x, lane = tid & 31, warp = tid >> 5;

    if (tid < 23) {
        int p = t0 - 15 + tid;
        s_tok[tid] = (p < 0) ? VV : tok[b * SS + p];
    }
    ((float4*)s_cb)[tid] = ((const float4*)conv_b)[tid]; // 256 * 4 = 1024
    __syncthreads();

    float4 acc[8];
#pragma unroll
    for (int i = 0; i < 8; ++i) acc[i] = ((const float4*)s_cb)[lane + 32 * i];

#pragma unroll 2
    for (int k = 0; k < KK; ++k) {
        const int v = s_tok[warp + k];
        const float4* row = (const float4*)(g_G + (size_t)(v * KK + k) * HH);
#pragma unroll
        for (int i = 0; i < 8; ++i) {
            float4 r = row[lane + 32 * i];
            acc[i].x += r.x; acc[i].y += r.y; acc[i].z += r.z; acc[i].w += r.w;
        }
    }
    float4* orow = (float4*)(g_act + (size_t)(b * SS + t0 + warp) * HH);
#pragma unroll
    for (int i = 0; i < 8; ++i)
        orow[lane + 32 * i] = make_float4(fmaxf(acc[i].x, 0.f), fmaxf(acc[i].y, 0.f),
                                          fmaxf(acc[i].z, 0.f), fmaxf(acc[i].w, 0.f));
}

// logits = L1[tok[row]] + lin_b + act[row]·lin_w[:,512:], then softmax.
// CTA tile: 32 rows x 256 v. warp owns 4 rows; lane owns v0=lane*8.
__global__ __launch_bounds__(256) void k_lin(const int* __restrict__ tok,
                                             const float* __restrict__ lin_w,
                                             const float* __restrict__ lin_b,
                                             float* __restrict__ out) {
    __shared__ __align__(16) float s_a[32 * 32];
    __shared__ __align__(16) float s_w[32 * 256];
    const int row0 = blockIdx.x * 32, tid = threadIdx.x;
    const int lane = tid & 31, warp = tid >> 5, v0 = lane * 8;

    u64 acc[4][4];
    const float4 lb0 = *(const float4*)(lin_b + v0);
    const float4 lb1 = *(const float4*)(lin_b + v0 + 4);
#pragma unroll
    for (int j = 0; j < 4; ++j) {
        const int vt = tok[row0 + warp * 4 + j];
        float4 p0 = *(const float4*)(g_L1 + vt * VV + v0);
        float4 p1 = *(const float4*)(g_L1 + vt * VV + v0 + 4);
        acc[j][0] = pack2(p0.x + lb0.x, p0.y + lb0.y);
        acc[j][1] = pack2(p0.z + lb0.z, p0.w + lb0.w);
        acc[j][2] = pack2(p1.x + lb1.x, p1.y + lb1.y);
        acc[j][3] = pack2(p1.z + lb1.z, p1.w + lb1.w);
    }

    const int ra = tid >> 3, pa = tid & 7;
    for (int h0 = 0; h0 < HH; h0 += 32) {
        *(float4*)(s_a + ra * 32 + pa * 4) =
            *(const float4*)(g_act + (size_t)(row0 + ra) * HH + h0 + pa * 4);
        const float* wr = lin_w + (size_t)tid * (EE + HH) + EE + h0;
#pragma unroll
        for (int j2 = 0; j2 < 8; ++j2) {
            float4 c = *(const float4*)(wr + j2 * 4);
            s_w[(j2 * 4 + 0) * 256 + tid] = c.x;
            s_w[(j2 * 4 + 1) * 256 + tid] = c.y;
            s_w[(j2 * 4 + 2) * 256 + tid] = c.z;
            s_w[(j2 * 4 + 3) * 256 + tid] = c.w;
        }
        __syncthreads();
#pragma unroll
        for (int kk = 0; kk < 32; ++kk) {
            ulonglong2 wa = *(const ulonglong2*)(s_w + kk * 256 + v0);
            ulonglong2 wb = *(const ulonglong2*)(s_w + kk * 256 + v0 + 4);
#pragma unroll
            for (int j = 0; j < 4; ++j) {
                float a = s_a[(warp * 4 + j) * 32 + kk];
                u64 ap = pack2(a, a);
                acc[j][0] = ffma2(ap, wa.x, acc[j][0]);
                acc[j][1] = ffma2(ap, wa.y, acc[j][1]);
                acc[j][2] = ffma2(ap, wb.x, acc[j][2]);
                acc[j][3] = ffma2(ap, wb.y, acc[j][3]);
            }
        }
        __syncthreads();
    }

#pragma unroll
    for (int j = 0; j < 4; ++j) {
        float v[8];
        unpack2(acc[j][0], v[0], v[1]); unpack2(acc[j][1], v[2], v[3]);
        unpack2(acc[j][2], v[4], v[5]); unpack2(acc[j][3], v[6], v[7]);
        float m = v[0];
#pragma unroll
        for (int i = 1; i < 8; ++i) m = fmaxf(m, v[i]);
#pragma unroll
        for (int off = 16; off; off >>= 1) m = fmaxf(m, __shfl_xor_sync(0xffffffffu, m, off));
        float s = 0.f;
#pragma unroll
        for (int i = 0; i < 8; ++i) { v[i] = __expf(v[i] - m); s += v[i]; }
#pragma unroll
        for (int off = 16; off; off >>= 1) s += __shfl_xor_sync(0xffffffffu, s, off);
        const float inv = __frcp_rn(s);
        float* op = out + (size_t)(row0 + warp * 4 + j) * VV + v0;
        *(float4*)op = make_float4(v[0] * inv, v[1] * inv, v[2] * inv, v[3] * inv);
        *(float4*)(op + 4) = make_float4(v[4] * inv, v[5] * inv, v[6] * inv, v[7] * inv);
    }
}

extern "C" void kernel_launch(void* const* d_in, const int* in_sizes, int n_in,
                              void* d_out, int out_size) {
    const int*   tok    = (const int*)d_in[0];
    const float* emb    = (const float*)d_in[1];
    const float* conv_w = (const float*)d_in[2];
    const float* conv_b = (const float*)d_in[3];
    const float* lin_w  = (const float*)d_in[4];
    const float* lin_b  = (const float*)d_in[5];
    float* out = (float*)d_out;

    k_L1<<<VV, 256>>>(emb, lin_w);
    k_zero<<<16, 256>>>();
    k_G<<<dim3(HH / 64, VV / 8), 256>>>(emb, conv_w);
    k_conv<<<(BB * SS) / 8, 256>>>(tok, conv_b);
    k_lin<<<(BB * SS) / 32, 256>>>(tok, lin_w, lin_b, out);
}

// round 9
// speedup vs baseline: 1.0028x; 1.0003x over previous
#include <cuda_runtime.h>

#define BB 32
#define SS 2048
#define VV 256
#define EE 512
#define HH 1024
#define KK 16

typedef unsigned long long u64;

__device__ __align__(256) float g_G[(VV + 1) * KK * HH];
__device__ __align__(256) float g_L1[VV * VV];
__device__ __align__(256) float g_act[(size_t)BB * SS * HH];

__device__ __forceinline__ u64 pack2(float lo, float hi) {
    u64 r; asm("mov.b64 %0,{%1,%2};" : "=l"(r) : "f"(lo), "f"(hi)); return r;
}
__device__ __forceinline__ void unpack2(u64 p, float& lo, float& hi) {
    asm("mov.b64 {%0,%1},%2;" : "=f"(lo), "=f"(hi) : "l"(p));
}
__device__ __forceinline__ u64 ffma2(u64 a, u64 b, u64 c) {
    u64 d; asm("fma.rn.f32x2 %0,%1,%2,%3;" : "=l"(d) : "l"(a), "l"(b), "l"(c)); return d;
}

// L1[vt][v] = emb[vt,:] . lin_w[v,0:512]
__global__ __launch_bounds__(256) void k_L1(const float* __restrict__ emb,
                                            const float* __restrict__ lin_w) {
    __shared__ __align__(16) float4 s_emb[EE / 4];
    const int vt = blockIdx.x, tid = threadIdx.x;
    if (tid < EE / 4) s_emb[tid] = ((const float4*)(emb + (size_t)vt * EE))[tid];
    __syncthreads();
    const int lane = tid & 31, warp = tid >> 5;
    for (int v = warp; v < VV; v += 8) {
        const float4* w4 = (const float4*)(lin_w + (size_t)v * (EE + HH));
        float s = 0.f;
#pragma unroll
        for (int i = 0; i < 4; ++i) {
            float4 a = s_emb[lane + 32 * i];
            float4 b = w4[lane + 32 * i];
            s += a.x * b.x + a.y * b.y + a.z * b.z + a.w * b.w;
        }
#pragma unroll
        for (int off = 16; off; off >>= 1) s += __shfl_xor_sync(0xffffffffu, s, off);
        if (lane == 0) g_L1[vt * VV + v] = s;
    }
}

// zero pad row G[VV][*][*]
__global__ __launch_bounds__(256) void k_zero() {
    ((float4*)(g_G + (size_t)VV * KK * HH))[blockIdx.x * 256 + threadIdx.x] =
        make_float4(0.f, 0.f, 0.f, 0.f);
}

// G[v][k][h] = sum_e emb[v,e] * conv_w[h,e,k]
__global__ __launch_bounds__(256) void k_G(const float* __restrict__ emb,
                                           const float* __restrict__ conv_w) {
    __shared__ __align__(16) float s_a[8 * 8];
    __shared__ __align__(16) float s_b[8 * KK * 64];
    const int h0 = blockIdx.x * 64, v0 = blockIdx.y * 8, tid = threadIdx.x;
    const int k = tid >> 4, hq = tid & 15;
    const int hl = tid >> 2, q = tid & 3;
    float acc[8][4];
#pragma unroll
    for (int v = 0; v < 8; ++v)
#pragma unroll
        for (int j = 0; j < 4; ++j) acc[v][j] = 0.f;

    for (int e0 = 0; e0 < EE; e0 += 8) {
        if (tid < 64) {
            int e = tid >> 3, v = tid & 7;
            s_a[e * 8 + v] = emb[(size_t)(v0 + v) * EE + e0 + e];
        }
#pragma unroll
        for (int e = 0; e < 8; ++e) {
            float4 w4 = *(const float4*)(conv_w + (size_t)(h0 + hl) * (EE * KK) +
                                         (e0 + e) * KK + q * 4);
            s_b[(e * KK + q * 4 + 0) * 64 + hl] = w4.x;
            s_b[(e * KK + q * 4 + 1) * 64 + hl] = w4.y;
            s_b[(e * KK + q * 4 + 2) * 64 + hl] = w4.z;
            s_b[(e * KK + q * 4 + 3) * 64 + hl] = w4.w;
        }
        __syncthreads();
#pragma unroll
        for (int e = 0; e < 8; ++e) {
            float4 a0 = *(const float4*)(s_a + e * 8);
            float4 a1 = *(const float4*)(s_a + e * 8 + 4);
            float a_[8] = {a0.x, a0.y, a0.z, a0.w, a1.x, a1.y, a1.z, a1.w};
            float4 bb = *(const float4*)(s_b + (e * KK + k) * 64 + hq * 4);
#pragma unroll
            for (int v = 0; v < 8; ++v) {
                acc[v][0] += a_[v] * bb.x;
                acc[v][1] += a_[v] * bb.y;
                acc[v][2] += a_[v] * bb.z;
                acc[v][3] += a_[v] * bb.w;
            }
        }
        __syncthreads();
    }
#pragma unroll
    for (int v = 0; v < 8; ++v)
        *(float4*)(g_G + (size_t)((v0 + v) * KK + k) * HH + h0 + hq * 4) =
            make_float4(acc[v][0], acc[v][1], acc[v][2], acc[v][3]);
}

// act[b,t,h] = relu(conv_b[h] + sum_k G[tok[t-15+k]][k][h]); one warp per timestep
__global__ __launch_bounds__(256) void k_conv(const int* __restrict__ tok,
                                              const float* __restrict__ conv_b) {
    __shared__ int s_tok[24];
    __shared__ __align__(16) float s_cb[HH];
    const int tile = blockIdx.x;
    const int b = tile >> 8;           // S/8 = 256 tiles per batch
    const int t0 = (tile & 255) << 3;
    const int tid = threadIdx.x, lane = tid & 31, warp = tid >> 5;

    if (tid < 23) {
        int p = t0 - 15 + tid;
        s_tok[tid] = (p < 0) ? VV : tok[b * SS + p];
    }
    ((float4*)s_cb)[tid] = ((const float4*)conv_b)[tid]; // 256 * 4 = 1024
    __syncthreads();

    float4 acc[8];
#pragma unroll
    for (int i = 0; i < 8; ++i) acc[i] = ((const float4*)s_cb)[lane + 32 * i];

#pragma unroll 2
    for (int k = 0; k < KK; ++k) {
        const int v = s_tok[warp + k];
        const float4* row = (const float4*)(g_G + (size_t)(v * KK + k) * HH);
#pragma unroll
        for (int i = 0; i < 8; ++i) {
            float4 r = row[lane + 32 * i];
            acc[i].x += r.x; acc[i].y += r.y; acc[i].z += r.z; acc[i].w += r.w;
        }
    }
    float4* orow = (float4*)(g_act + (size_t)(b * SS + t0 + warp) * HH);
#pragma unroll
    for (int i = 0; i < 8; ++i)
        orow[lane + 32 * i] = make_float4(fmaxf(acc[i].x, 0.f), fmaxf(acc[i].y, 0.f),
                                          fmaxf(acc[i].z, 0.f), fmaxf(acc[i].w, 0.f));
}

// logits = L1[tok[row]] + lin_b + act[row]·lin_w[:,512:], then softmax.
// CTA tile: 32 rows x 256 v. warp owns 4 rows; lane owns v0=lane*8.
__global__ __launch_bounds__(256) void k_lin(const int* __restrict__ tok,
                                             const float* __restrict__ lin_w,
                                             const float* __restrict__ lin_b,
                                             float* __restrict__ out) {
    __shared__ __align__(16) float s_a[32 * 32];
    __shared__ __align__(16) float s_w[32 * 256];
    const int row0 = blockIdx.x * 32, tid = threadIdx.x;
    const int lane = tid & 31, warp = tid >> 5, v0 = lane * 8;

    u64 acc[4][4];
    const float4 lb0 = *(const float4*)(lin_b + v0);
    const float4 lb1 = *(const float4*)(lin_b + v0 + 4);
#pragma unroll
    for (int j = 0; j < 4; ++j) {
        const int vt = tok[row0 + warp * 4 + j];
        float4 p0 = *(const float4*)(g_L1 + vt * VV + v0);
        float4 p1 = *(const float4*)(g_L1 + vt * VV + v0 + 4);
        acc[j][0] = pack2(p0.x + lb0.x, p0.y + lb0.y);
        acc[j][1] = pack2(p0.z + lb0.z, p0.w + lb0.w);
        acc[j][2] = pack2(p1.x + lb1.x, p1.y + lb1.y);
        acc[j][3] = pack2(p1.z + lb1.z, p1.w + lb1.w);
    }

    const int ra = tid >> 3, pa = tid & 7;
    for (int h0 = 0; h0 < HH; h0 += 32) {
        *(float4*)(s_a + ra * 32 + pa * 4) =
            *(const float4*)(g_act + (size_t)(row0 + ra) * HH + h0 + pa * 4);
        const float* wr = lin_w + (size_t)tid * (EE + HH) + EE + h0;
#pragma unroll
        for (int j2 = 0; j2 < 8; ++j2) {
            float4 c = *(const float4*)(wr + j2 * 4);
            s_w[(j2 * 4 + 0) * 256 + tid] = c.x;
            s_w[(j2 * 4 + 1) * 256 + tid] = c.y;
            s_w[(j2 * 4 + 2) * 256 + tid] = c.z;
            s_w[(j2 * 4 + 3) * 256 + tid] = c.w;
        }
        __syncthreads();
#pragma unroll
        for (int kk = 0; kk < 32; ++kk) {
            ulonglong2 wa = *(const ulonglong2*)(s_w + kk * 256 + v0);
            ulonglong2 wb = *(const ulonglong2*)(s_w + kk * 256 + v0 + 4);
#pragma unroll
            for (int j = 0; j < 4; ++j) {
                float a = s_a[(warp * 4 + j) * 32 + kk];
                u64 ap = pack2(a, a);
                acc[j][0] = ffma2(ap, wa.x, acc[j][0]);
                acc[j][1] = ffma2(ap, wa.y, acc[j][1]);
                acc[j][2] = ffma2(ap, wb.x, acc[j][2]);
                acc[j][3] = ffma2(ap, wb.y, acc[j][3]);
            }
        }
        __syncthreads();
    }

#pragma unroll
    for (int j = 0; j < 4; ++j) {
        float v[8];
        unpack2(acc[j][0], v[0], v[1]); unpack2(acc[j][1], v[2], v[3]);
        unpack2(acc[j][2], v[4], v[5]); unpack2(acc[j][3], v[6], v[7]);
        float m = v[0];
#pragma unroll
        for (int i = 1; i < 8; ++i) m = fmaxf(m, v[i]);
#pragma unroll
        for (int off = 16; off; off >>= 1) m = fmaxf(m, __shfl_xor_sync(0xffffffffu, m, off));
        float s = 0.f;
#pragma unroll
        for (int i = 0; i < 8; ++i) { v[i] = __expf(v[i] - m); s += v[i]; }
#pragma unroll
        for (int off = 16; off; off >>= 1) s += __shfl_xor_sync(0xffffffffu, s, off);
        const float inv = __frcp_rn(s);
        float* op = out + (size_t)(row0 + warp * 4 + j) * VV + v0;
        *(float4*)op = make_float4(v[0] * inv, v[1] * inv, v[2] * inv, v[3] * inv);
        *(float4*)(op + 4) = make_float4(v[4] * inv, v[5] * inv, v[6] * inv, v[7] * inv);
    }
}

extern "C" void kernel_launch(void* const* d_in, const int* in_sizes, int n_in,
                              void* d_out, int out_size) {
    const int*   tok    = (const int*)d_in[0];
    const float* emb    = (const float*)d_in[1];
    const float* conv_w = (const float*)d_in[2];
    const float* conv_b = (const float*)d_in[3];
    const float* lin_w  = (const float*)d_in[4];
    const float* lin_b  = (const float*)d_in[5];
    float* out = (float*)d_out;

    k_L1<<<VV, 256>>>(emb, lin_w);
    k_zero<<<16, 256>>>();
    k_G<<<dim3(HH / 64, VV / 8), 256>>>(emb, conv_w);
    k_conv<<<(BB * SS) / 8, 256>>>(tok, conv_b);
    k_lin<<<(BB * SS) / 32, 256>>>(tok, lin_w, lin_b, out);
}